// round 1
// baseline (speedup 1.0000x reference)
#include <cuda_runtime.h>
#include <math.h>

#define N_NODES 50000
#define N_EDGES 1600000
#define DIM     128
#define NHEADS  4
#define NEG_SLOPE 0.2f

// ---------------- scratch (static device arrays; no allocation) ----------------
__device__ float    g_hq   [N_NODES * NHEADS];
__device__ float    g_kact [N_NODES * NHEADS];
__device__ float    g_qagg [N_NODES * NHEADS];
__device__ unsigned g_maxs [N_NODES * NHEADS];
__device__ float    g_sume [N_NODES * NHEADS];
__device__ float    g_ex   [(size_t)N_EDGES * NHEADS];   // scores, then exp(scores-max)
__device__ float    g_hproj[(size_t)N_NODES * DIM];

// ---------------- helpers ----------------
static __device__ __forceinline__ float leaky_f(float v) {
    return v >= 0.f ? v : NEG_SLOPE * v;
}

// orderable-uint encoding for float atomicMax
static __device__ __forceinline__ unsigned enc_f(float f) {
    unsigned b = __float_as_uint(f);
    return (b & 0x80000000u) ? ~b : (b | 0x80000000u);
}
static __device__ __forceinline__ float dec_f(unsigned u) {
    return (u & 0x80000000u) ? __uint_as_float(u ^ 0x80000000u)
                             : __uint_as_float(~u);
}

static __device__ __forceinline__ void red_add_v4(float* p, float a, float b, float c, float d) {
    asm volatile("red.global.add.v4.f32 [%0], {%1,%2,%3,%4};"
                 :: "l"(p), "f"(a), "f"(b), "f"(c), "f"(d) : "memory");
}

static __device__ __forceinline__ unsigned long long pack2(float lo, float hi) {
    unsigned long long r;
    asm("mov.b64 %0, {%1,%2};" : "=l"(r) : "f"(lo), "f"(hi));
    return r;
}
static __device__ __forceinline__ void unpack2(unsigned long long v, float& lo, float& hi) {
    asm("mov.b64 {%0,%1}, %2;" : "=f"(lo), "=f"(hi) : "l"(v));
}

// ---------------- kernels ----------------

// zero out accumulators (out is poisoned; must be re-zeroed every launch for graph replay)
__global__ void k_init(float4* __restrict__ out) {
    int i = blockIdx.x * blockDim.x + threadIdx.x;
    if (i < N_NODES * DIM / 4) out[i] = make_float4(0.f, 0.f, 0.f, 0.f);
    if (i < N_NODES) {
        ((float4*)g_qagg)[i] = make_float4(0.f, 0.f, 0.f, 0.f);
        ((float4*)g_sume)[i] = make_float4(0.f, 0.f, 0.f, 0.f);
        ((uint4*)g_maxs)[i]  = make_uint4(0u, 0u, 0u, 0u);
    }
}

// per-node h_q = x@Wq^T, k_act = leaky(x@Wk^T). One warp per node.
__global__ void k_qk(const float* __restrict__ x,
                     const float* __restrict__ Wq,
                     const float* __restrict__ Wk) {
    int warp = (blockIdx.x * blockDim.x + threadIdx.x) >> 5;
    if (warp >= N_NODES) return;
    int lane = threadIdx.x & 31;

    float4 xv = *(const float4*)&x[(size_t)warp * DIM + lane * 4];
    float q[NHEADS], k[NHEADS];
#pragma unroll
    for (int h = 0; h < NHEADS; h++) {
        float4 wq = *(const float4*)&Wq[h * DIM + lane * 4];
        float4 wk = *(const float4*)&Wk[h * DIM + lane * 4];
        q[h] = xv.x * wq.x + xv.y * wq.y + xv.z * wq.z + xv.w * wq.w;
        k[h] = xv.x * wk.x + xv.y * wk.y + xv.z * wk.z + xv.w * wk.w;
    }
#pragma unroll
    for (int off = 16; off > 0; off >>= 1) {
#pragma unroll
        for (int h = 0; h < NHEADS; h++) {
            q[h] += __shfl_xor_sync(0xffffffffu, q[h], off);
            k[h] += __shfl_xor_sync(0xffffffffu, k[h], off);
        }
    }
    if (lane == 0) {
#pragma unroll
        for (int h = 0; h < NHEADS; h++) {
            g_hq[warp * NHEADS + h]   = q[h];
            g_kact[warp * NHEADS + h] = leaky_f(k[h]);
        }
    }
}

// h_proj = x @ Wl^T + bl : 128x128 tile per block, packed f32x2 FMA.
__global__ __launch_bounds__(256) void k_gemm(const float* __restrict__ x,
                                              const float* __restrict__ Wl,
                                              const float* __restrict__ bl) {
    __shared__ float xs[32][DIM];  // xs[k][m] (x tile, transposed)
    __shared__ float ws[32][DIM];  // ws[k][o] (Wl tile, transposed)

    const int tid = threadIdx.x;
    const int tm = tid >> 4;   // 0..15 -> 8 m-rows each
    const int tn = tid & 15;   // 0..15 -> 8 outs (4 pairs spaced 32)
    const int m0 = blockIdx.x * 128;

    unsigned long long acc[8][4];
#pragma unroll
    for (int i = 0; i < 8; i++)
#pragma unroll
        for (int j = 0; j < 4; j++) acc[i][j] = 0ull;

    const int lrow = tid >> 1;          // 0..127
    const int lk   = (tid & 1) * 16;    // 0 / 16

    for (int k0 = 0; k0 < DIM; k0 += 32) {
        __syncthreads();
        {   // x tile (transposed store)
            int gm = m0 + lrow;
#pragma unroll
            for (int q = 0; q < 16; q += 4) {
                float4 v = make_float4(0.f, 0.f, 0.f, 0.f);
                if (gm < N_NODES)
                    v = *(const float4*)&x[(size_t)gm * DIM + k0 + lk + q];
                xs[lk + q + 0][lrow] = v.x;
                xs[lk + q + 1][lrow] = v.y;
                xs[lk + q + 2][lrow] = v.z;
                xs[lk + q + 3][lrow] = v.w;
            }
        }
        {   // Wl tile (transposed store)
#pragma unroll
            for (int q = 0; q < 16; q += 4) {
                float4 w = *(const float4*)&Wl[(size_t)lrow * DIM + k0 + lk + q];
                ws[lk + q + 0][lrow] = w.x;
                ws[lk + q + 1][lrow] = w.y;
                ws[lk + q + 2][lrow] = w.z;
                ws[lk + q + 3][lrow] = w.w;
            }
        }
        __syncthreads();

#pragma unroll 8
        for (int kk = 0; kk < 32; kk++) {
            float4 a0 = *(const float4*)&xs[kk][tm * 8];
            float4 a1 = *(const float4*)&xs[kk][tm * 8 + 4];
            unsigned long long a2[8];
            a2[0] = pack2(a0.x, a0.x); a2[1] = pack2(a0.y, a0.y);
            a2[2] = pack2(a0.z, a0.z); a2[3] = pack2(a0.w, a0.w);
            a2[4] = pack2(a1.x, a1.x); a2[5] = pack2(a1.y, a1.y);
            a2[6] = pack2(a1.z, a1.z); a2[7] = pack2(a1.w, a1.w);
            unsigned long long b2[4];
#pragma unroll
            for (int j = 0; j < 4; j++) {
                float2 b = *(const float2*)&ws[kk][tn * 2 + 32 * j];
                b2[j] = pack2(b.x, b.y);
            }
#pragma unroll
            for (int i = 0; i < 8; i++)
#pragma unroll
                for (int j = 0; j < 4; j++)
                    asm volatile("fma.rn.f32x2 %0, %1, %2, %0;"
                                 : "+l"(acc[i][j]) : "l"(a2[i]), "l"(b2[j]));
        }
    }

#pragma unroll
    for (int j = 0; j < 4; j++) {
        int o = tn * 2 + 32 * j;
        float2 blv = *(const float2*)&bl[o];
#pragma unroll
        for (int i = 0; i < 8; i++) {
            int m = m0 + tm * 8 + i;
            if (m < N_NODES) {
                float lo, hi;
                unpack2(acc[i][j], lo, hi);
                float2 r = make_float2(lo + blv.x, hi + blv.y);
                *(float2*)&g_hproj[(size_t)m * DIM + o] = r;
            }
        }
    }
}

// q_agg[row] += h_q[col]
__global__ void k_qagg(const int* __restrict__ ei) {
    int e = blockIdx.x * blockDim.x + threadIdx.x;
    if (e >= N_EDGES) return;
    int row = ei[e], col = ei[N_EDGES + e];
    float4 h = ((const float4*)g_hq)[col];
    red_add_v4(&g_qagg[row * NHEADS], h.x, h.y, h.z, h.w);
}

// scores = k_act[row] * q_agg[col]; segment max by row
__global__ void k_score(const int* __restrict__ ei) {
    int e = blockIdx.x * blockDim.x + threadIdx.x;
    if (e >= N_EDGES) return;
    int row = ei[e], col = ei[N_EDGES + e];
    float4 k = ((const float4*)g_kact)[row];
    float4 q = ((const float4*)g_qagg)[col];
    float4 s = make_float4(k.x * q.x, k.y * q.y, k.z * q.z, k.w * q.w);
    ((float4*)g_ex)[e] = s;
    atomicMax(&g_maxs[row * NHEADS + 0], enc_f(s.x));
    atomicMax(&g_maxs[row * NHEADS + 1], enc_f(s.y));
    atomicMax(&g_maxs[row * NHEADS + 2], enc_f(s.z));
    atomicMax(&g_maxs[row * NHEADS + 3], enc_f(s.w));
}

// ex = exp(s - max); segment sum by row
__global__ void k_expsum(const int* __restrict__ ei) {
    int e = blockIdx.x * blockDim.x + threadIdx.x;
    if (e >= N_EDGES) return;
    int row = ei[e];
    float4 s = ((const float4*)g_ex)[e];
    uint4 mu = ((const uint4*)g_maxs)[row];
    float4 ex = make_float4(expf(s.x - dec_f(mu.x)),
                            expf(s.y - dec_f(mu.y)),
                            expf(s.z - dec_f(mu.z)),
                            expf(s.w - dec_f(mu.w)));
    ((float4*)g_ex)[e] = ex;
    red_add_v4(&g_sume[row * NHEADS], ex.x, ex.y, ex.z, ex.w);
}

// sume -> 1/(sume + 1e-8)
__global__ void k_recip() {
    int i = blockIdx.x * blockDim.x + threadIdx.x;
    if (i < N_NODES * NHEADS) g_sume[i] = 1.f / (g_sume[i] + 1e-8f);
}

// out[row] += alpha_mean(e) * h_proj[col] ; one warp per edge
__global__ void k_agg(const int* __restrict__ ei, float* __restrict__ out) {
    int t = blockIdx.x * blockDim.x + threadIdx.x;
    int e = t >> 5;
    if (e >= N_EDGES) return;
    int lane = threadIdx.x & 31;
    int row = __ldg(&ei[e]);
    int col = __ldg(&ei[N_EDGES + e]);
    float4 ex  = ((const float4*)g_ex)[e];
    float4 inv = ((const float4*)g_sume)[row];
    float alpha = 0.25f * (ex.x * inv.x + ex.y * inv.y + ex.z * inv.z + ex.w * inv.w);
    float4 v = *(const float4*)&g_hproj[(size_t)col * DIM + lane * 4];
    red_add_v4(&out[(size_t)row * DIM + lane * 4],
               alpha * v.x, alpha * v.y, alpha * v.z, alpha * v.w);
}

// out = leaky(out)
__global__ void k_leaky(float4* __restrict__ out) {
    int i = blockIdx.x * blockDim.x + threadIdx.x;
    if (i >= N_NODES * DIM / 4) return;
    float4 v = out[i];
    v.x = leaky_f(v.x); v.y = leaky_f(v.y); v.z = leaky_f(v.z); v.w = leaky_f(v.w);
    out[i] = v;
}

// ---------------- launch ----------------
extern "C" void kernel_launch(void* const* d_in, const int* in_sizes, int n_in,
                              void* d_out, int out_size) {
    const float* x  = (const float*)d_in[0];
    const int*   ei = (const int*)d_in[1];
    const float* Wq = (const float*)d_in[2];
    const float* Wk = (const float*)d_in[3];
    const float* Wl = (const float*)d_in[4];
    const float* bl = (const float*)d_in[5];
    float* out = (float*)d_out;

    const int TB = 256;
    const int EDGE_BLOCKS = (N_EDGES + TB - 1) / TB;          // 6250
    const int VEC_BLOCKS  = (N_NODES * DIM / 4 + TB - 1) / TB; // 6250

    k_init<<<VEC_BLOCKS, TB>>>((float4*)out);
    k_qk<<<(N_NODES * 32 + TB - 1) / TB, TB>>>(x, Wq, Wk);
    k_gemm<<<(N_NODES + 127) / 128, TB>>>(x, Wl, bl);
    k_qagg<<<EDGE_BLOCKS, TB>>>(ei);
    k_score<<<EDGE_BLOCKS, TB>>>(ei);
    k_expsum<<<EDGE_BLOCKS, TB>>>(ei);
    k_recip<<<(N_NODES * NHEADS + TB - 1) / TB, TB>>>();
    k_agg<<<(N_EDGES * 32 + TB - 1) / TB, TB>>>(ei, out);
    k_leaky<<<VEC_BLOCKS, TB>>>((float4*)out);
}